// round 15
// baseline (speedup 1.0000x reference)
#include <cuda_runtime.h>
#include <cstdint>

// CompressK: mean-pool over sliding windows of 32 rows, stride 16.
// k: (BATCH*SEQ_LEN, 4, 128) fp32 -> row = 512 floats = 2 KB
// out: (4092, 4, 128) fp32 followed by cu_comp (BATCH+1) as fp32 values.
//
// Bulk-async pipeline: each 16-row block-sum tile = 32 KB CONTIGUOUS in
// gmem. cp.async.bulk streams tiles into a 6-stage smem ring (192 KB,
// mbarrier complete_tx); the DMA engine runs ahead independent of the
// consumer warps' barriers -- decoupling load issue from compute, which
// was the plateau of all register-resident variants (<=5.8 TB/s).
// Consumers: 512 threads, scalar column each, 16 LDS.32 per tile.

#define BATCH 4
#define SEQ_LEN 16384
#define ROW_FLOATS 512
#define CHUNKS_PER_BATCH 1023     // (16384-32)/16 + 1
#define TOTAL_CHUNKS (BATCH * CHUNKS_PER_BATCH)   // 4092
#define CH 8
#define SEGS_PER_BATCH ((CHUNKS_PER_BATCH + CH - 1) / CH)    // 128
#define OUT_FLOATS ((size_t)TOTAL_CHUNKS * ROW_FLOATS)       // 2,095,104
#define NTHREADS 512

#define STAGES 6
#define TILE_ROWS 16
#define TILE_FLOATS (TILE_ROWS * ROW_FLOATS)     // 8192
#define TILE_BYTES (TILE_FLOATS * 4)             // 32768
#define SMEM_TILES_BYTES (STAGES * TILE_BYTES)   // 196608
#define SMEM_TOTAL (SMEM_TILES_BYTES + 64)       // + mbarriers

__device__ __forceinline__ uint32_t smem_u32(const void* p) {
    uint32_t a;
    asm("{ .reg .u64 t; cvta.to.shared.u64 t, %1; cvt.u32.u64 %0, t; }"
        : "=r"(a) : "l"(p));
    return a;
}

__global__ __launch_bounds__(NTHREADS, 1) void compress_k_kernel(
    const float* __restrict__ k, float* __restrict__ out)
{
    extern __shared__ float smem[];
    const uint32_t smem_base = smem_u32(smem);
    const uint32_t mbar_base = smem_base + SMEM_TILES_BYTES;   // 6 x u64

    const int tid = threadIdx.x;            // 0..511, scalar column
    const int batch = blockIdx.x / SEGS_PER_BATCH;
    const int seg   = blockIdx.x % SEGS_PER_BATCH;

    // Fused cu_comp tail (fp32 values; exact for these magnitudes)
    if (blockIdx.x == 0 && tid <= BATCH) {
        out[OUT_FLOATS + tid] = (float)(tid * CHUNKS_PER_BATCH);
    }

    const int c_begin = seg * CH;
    int nch = CHUNKS_PER_BATCH - c_begin;
    if (nch > CH) nch = CH;                  // 8, or 7 on the last segment
    const int ntiles = nch + 1;              // block-sums needed

    // init mbarriers (count = 1: the producer's arrive.expect_tx)
    if (tid == 0) {
        #pragma unroll
        for (int s = 0; s < STAGES; ++s) {
            asm volatile("mbarrier.init.shared.b64 [%0], %1;"
                         :: "r"(mbar_base + s * 8), "r"(1u) : "memory");
        }
    }
    __syncthreads();

    const size_t base_row = (size_t)batch * SEQ_LEN + (size_t)c_begin * 16;
    const float* seg_src = k + base_row * ROW_FLOATS;

    // producer: issue tile j into stage j % STAGES
    auto issue = [&](int j) {
        const uint32_t mb = mbar_base + (uint32_t)(j % STAGES) * 8;
        const uint32_t dst = smem_base + (uint32_t)(j % STAGES) * TILE_BYTES;
        const float* src = seg_src + (size_t)j * TILE_FLOATS;
        asm volatile("mbarrier.arrive.expect_tx.shared.b64 _, [%0], %1;"
                     :: "r"(mb), "r"((uint32_t)TILE_BYTES) : "memory");
        asm volatile(
            "cp.async.bulk.shared::cluster.global.mbarrier::complete_tx::bytes "
            "[%0], [%1], %2, [%3];"
            :: "r"(dst), "l"(src), "r"((uint32_t)TILE_BYTES), "r"(mb)
            : "memory");
    };

    // prologue: fill the pipeline
    if (tid == 0) {
        const int npro = ntiles < STAGES ? ntiles : STAGES;
        for (int j = 0; j < npro; ++j) issue(j);
    }

    const float inv32 = 1.0f / 32.0f;
    float sPrev = 0.0f;
    const size_t out_base =
        ((size_t)batch * CHUNKS_PER_BATCH + c_begin) * ROW_FLOATS + tid;

    for (int j = 0; j < ntiles; ++j) {
        const int s = j % STAGES;
        const uint32_t ph = (uint32_t)((j / STAGES) & 1);
        const uint32_t mb = mbar_base + (uint32_t)s * 8;

        // wait for tile j
        uint32_t done;
        do {
            asm volatile(
                "{\n\t.reg .pred p;\n\t"
                "mbarrier.try_wait.parity.shared.b64 p, [%1], %2, 0x989680;\n\t"
                "selp.b32 %0, 1, 0, p;\n\t}"
                : "=r"(done) : "r"(mb), "r"(ph) : "memory");
        } while (!done);

        // sum 16 rows of scalar column tid (conflict-free LDS.32)
        const float* tile = smem + (size_t)s * TILE_FLOATS + tid;
        float a0 = 0.f, a1 = 0.f, a2 = 0.f, a3 = 0.f;
        #pragma unroll
        for (int r = 0; r < 4; ++r) {
            a0 += tile[(4 * r + 0) * ROW_FLOATS];
            a1 += tile[(4 * r + 1) * ROW_FLOATS];
            a2 += tile[(4 * r + 2) * ROW_FLOATS];
            a3 += tile[(4 * r + 3) * ROW_FLOATS];
        }
        float sCur = (a0 + a1) + (a2 + a3);

        if (j > 0) {
            out[out_base + (size_t)(j - 1) * ROW_FLOATS] = (sPrev + sCur) * inv32;
        }
        sPrev = sCur;

        // all threads done reading stage s -> producer may refill it
        __syncthreads();
        if (tid == 0 && j + STAGES < ntiles) issue(j + STAGES);
    }
}

extern "C" void kernel_launch(void* const* d_in, const int* in_sizes, int n_in,
                              void* d_out, int out_size)
{
    const float* k = (const float*)d_in[0];

    cudaFuncSetAttribute(compress_k_kernel,
                         cudaFuncAttributeMaxDynamicSharedMemorySize, SMEM_TOTAL);

    dim3 grid(BATCH * SEGS_PER_BATCH);   // 512
    compress_k_kernel<<<grid, NTHREADS, SMEM_TOTAL>>>(k, (float*)d_out);
}

// round 16
// speedup vs baseline: 1.1018x; 1.1018x over previous
#include <cuda_runtime.h>
#include <cstdint>

// CompressK: mean-pool over sliding windows of 32 rows, stride 16.
// k: (BATCH*SEQ_LEN, 4, 128) fp32 -> row = 512 floats = 2 KB
// out: (4092, 4, 128) fp32 followed by cu_comp (BATCH+1) as fp32 values.
//
// Bulk-async pipeline v2:
//  - 3-stage x 32 KB smem ring (96 KB) -> 2 blocks/SM co-resident
//    (overlapping prologues/tails across blocks).
//  - Dedicated producer warp (warp 16) + empty-mbarriers (count = 16
//    consumer warps): stage recycling is decoupled from block barriers,
//    so the DMA stream never waits on compute/store scheduling.
// Consumers: 512 threads, one scalar column each, 16 LDS.32 per tile.

#define BATCH 4
#define SEQ_LEN 16384
#define ROW_FLOATS 512
#define CHUNKS_PER_BATCH 1023     // (16384-32)/16 + 1
#define TOTAL_CHUNKS (BATCH * CHUNKS_PER_BATCH)   // 4092
#define CH 8
#define SEGS_PER_BATCH ((CHUNKS_PER_BATCH + CH - 1) / CH)    // 128
#define OUT_FLOATS ((size_t)TOTAL_CHUNKS * ROW_FLOATS)       // 2,095,104

#define NCONS 512                 // consumer threads (cols)
#define NTHREADS 544              // + 1 producer warp
#define NWARPS_CONS 16

#define STAGES 3
#define TILE_ROWS 16
#define TILE_FLOATS (TILE_ROWS * ROW_FLOATS)     // 8192
#define TILE_BYTES (TILE_FLOATS * 4)             // 32768
#define SMEM_TILES_BYTES (STAGES * TILE_BYTES)   // 98304
#define SMEM_TOTAL (SMEM_TILES_BYTES + 2 * STAGES * 8)

__device__ __forceinline__ uint32_t smem_u32(const void* p) {
    uint32_t a;
    asm("{ .reg .u64 t; cvta.to.shared.u64 t, %1; cvt.u32.u64 %0, t; }"
        : "=r"(a) : "l"(p));
    return a;
}

__global__ __launch_bounds__(NTHREADS, 2) void compress_k_kernel(
    const float* __restrict__ k, float* __restrict__ out)
{
    extern __shared__ float smem[];
    const uint32_t smem_base  = smem_u32(smem);
    const uint32_t full_base  = smem_base + SMEM_TILES_BYTES;          // 3 x u64
    const uint32_t empty_base = full_base + STAGES * 8;                // 3 x u64

    const int tid = threadIdx.x;
    const int batch = blockIdx.x / SEGS_PER_BATCH;
    const int seg   = blockIdx.x % SEGS_PER_BATCH;

    // Fused cu_comp tail (fp32 values; exact for these magnitudes)
    if (blockIdx.x == 0 && tid <= BATCH) {
        out[OUT_FLOATS + tid] = (float)(tid * CHUNKS_PER_BATCH);
    }

    const int c_begin = seg * CH;
    int nch = CHUNKS_PER_BATCH - c_begin;
    if (nch > CH) nch = CH;                  // 8, or 7 on the last segment
    const int ntiles = nch + 1;              // block-sums needed

    if (tid == 0) {
        #pragma unroll
        for (int s = 0; s < STAGES; ++s) {
            asm volatile("mbarrier.init.shared.b64 [%0], %1;"
                         :: "r"(full_base + s * 8), "r"(1u) : "memory");
            asm volatile("mbarrier.init.shared.b64 [%0], %1;"
                         :: "r"(empty_base + s * 8), "r"((uint32_t)NWARPS_CONS)
                         : "memory");
        }
    }
    __syncthreads();

    const size_t base_row = (size_t)batch * SEQ_LEN + (size_t)c_begin * 16;
    const float* seg_src = k + base_row * ROW_FLOATS;

    if (tid >= NCONS) {
        // ---------------- producer warp ----------------
        if (tid == NCONS) {                  // one thread issues
            int s = 0, eph = 1;              // empty-cursor: first waits pass
            for (int j = 0; j < ntiles; ++j) {
                const uint32_t emb = empty_base + (uint32_t)s * 8;
                uint32_t done;
                do {
                    asm volatile(
                        "{\n\t.reg .pred p;\n\t"
                        "mbarrier.try_wait.parity.shared.b64 p, [%1], %2, 0x989680;\n\t"
                        "selp.b32 %0, 1, 0, p;\n\t}"
                        : "=r"(done) : "r"(emb), "r"((uint32_t)eph) : "memory");
                } while (!done);

                const uint32_t fmb = full_base + (uint32_t)s * 8;
                const uint32_t dst = smem_base + (uint32_t)s * TILE_BYTES;
                const float* src = seg_src + (size_t)j * TILE_FLOATS;
                asm volatile("mbarrier.arrive.expect_tx.shared.b64 _, [%0], %1;"
                             :: "r"(fmb), "r"((uint32_t)TILE_BYTES) : "memory");
                asm volatile(
                    "cp.async.bulk.shared::cluster.global.mbarrier::complete_tx::bytes "
                    "[%0], [%1], %2, [%3];"
                    :: "r"(dst), "l"(src), "r"((uint32_t)TILE_BYTES), "r"(fmb)
                    : "memory");

                if (++s == STAGES) { s = 0; eph ^= 1; }
            }
        }
    } else {
        // ---------------- consumer threads (one scalar column) ----------------
        const int lane = tid & 31;
        const float inv32 = 1.0f / 32.0f;
        float sPrev = 0.0f;
        const size_t out_base =
            ((size_t)batch * CHUNKS_PER_BATCH + c_begin) * ROW_FLOATS + tid;

        int s = 0, fph = 0;
        for (int j = 0; j < ntiles; ++j) {
            const uint32_t fmb = full_base + (uint32_t)s * 8;
            uint32_t done;
            do {
                asm volatile(
                    "{\n\t.reg .pred p;\n\t"
                    "mbarrier.try_wait.parity.shared.b64 p, [%1], %2, 0x989680;\n\t"
                    "selp.b32 %0, 1, 0, p;\n\t}"
                    : "=r"(done) : "r"(fmb), "r"((uint32_t)fph) : "memory");
            } while (!done);

            // sum 16 rows of scalar column tid (conflict-free LDS.32)
            const float* tile = smem + (size_t)s * TILE_FLOATS + tid;
            float a0 = 0.f, a1 = 0.f, a2 = 0.f, a3 = 0.f;
            #pragma unroll
            for (int r = 0; r < 4; ++r) {
                a0 += tile[(4 * r + 0) * ROW_FLOATS];
                a1 += tile[(4 * r + 1) * ROW_FLOATS];
                a2 += tile[(4 * r + 2) * ROW_FLOATS];
                a3 += tile[(4 * r + 3) * ROW_FLOATS];
            }
            float sCur = (a0 + a1) + (a2 + a3);

            // this warp is done with stage s -> one arrival per warp
            if (lane == 0) {
                asm volatile("mbarrier.arrive.shared.b64 _, [%0];"
                             :: "r"(empty_base + (uint32_t)s * 8) : "memory");
            }

            if (j > 0) {
                out[out_base + (size_t)(j - 1) * ROW_FLOATS] = (sPrev + sCur) * inv32;
            }
            sPrev = sCur;

            if (++s == STAGES) { s = 0; fph ^= 1; }
        }
    }
}

extern "C" void kernel_launch(void* const* d_in, const int* in_sizes, int n_in,
                              void* d_out, int out_size)
{
    const float* k = (const float*)d_in[0];

    cudaFuncSetAttribute(compress_k_kernel,
                         cudaFuncAttributeMaxDynamicSharedMemorySize, SMEM_TOTAL);

    dim3 grid(BATCH * SEGS_PER_BATCH);   // 512
    compress_k_kernel<<<grid, NTHREADS, SMEM_TOTAL>>>(k, (float*)d_out);
}